// round 16
// baseline (speedup 1.0000x reference)
#include <cuda_runtime.h>
#include <cuda_fp16.h>
#include <cfloat>
#include <cstdint>

#define NV 16
#define NN 8192
#define ND 256
#define NK 1024
#define W1 0.26f          // coarse-score uncertainty window
#define MARGIN 0.05f      // fp32-exact pair-adjudication margin

// ---- smem layout (bytes) ----
#define ROWB   144
#define ATILB  18432
#define BTILB  9216
#define AOFF   0
#define BOFF   73728
#define WSQ_S  101376
#define MRG    105472
#define SMEM_TOTAL 111616

// ---- device scratch ----
__device__ float  g_wsq[NV * NK];
__device__ float  g_Wt[(size_t)NV * NK * ND];                    // [V][K][D] fp32
__device__ __align__(256) __half g_Wh[(size_t)NV * NK * ND];     // Wt fp16
__device__ int    g_idx[NV * NN];
__device__ int    g_fix_count;
__device__ int    g_pair_count;
__device__ int    g_fix_rows[NV * NN];
__device__ int    g_pair_rows[NV * NN];
__device__ int2   g_pair_cands[NV * NN];
__device__ double g_accum;

// ---- helpers ----
__device__ __forceinline__ uint32_t smem_u32(const void* p) {
    uint32_t a;
    asm("{ .reg .u64 t; cvta.to.shared.u64 t, %1; cvt.u32.u64 %0, t; }" : "=r"(a) : "l"(p));
    return a;
}
__device__ __forceinline__ void cpa16(uint32_t dst, const void* src) {
    asm volatile("cp.async.cg.shared.global [%0], [%1], 16;" :: "r"(dst), "l"(src));
}
#define CP_COMMIT() asm volatile("cp.async.commit_group;" ::: "memory")
#define CP_WAIT1()  asm volatile("cp.async.wait_group 1;" ::: "memory")
#define CP_WAIT0()  asm volatile("cp.async.wait_group 0;" ::: "memory")
__device__ __forceinline__ void ldsm4(uint32_t* r, uint32_t a) {
    asm volatile("ldmatrix.sync.aligned.m8n8.x4.shared.b16 {%0,%1,%2,%3}, [%4];"
        : "=r"(r[0]), "=r"(r[1]), "=r"(r[2]), "=r"(r[3]) : "r"(a));
}
__device__ __forceinline__ void mma16816(float* c, const uint32_t* a, const uint32_t* b) {
    asm volatile("mma.sync.aligned.m16n8k16.row.col.f32.f16.f16.f32 "
        "{%0,%1,%2,%3}, {%4,%5,%6,%7}, {%8,%9}, {%0,%1,%2,%3};"
        : "+f"(c[0]), "+f"(c[1]), "+f"(c[2]), "+f"(c[3])
        : "r"(a[0]), "r"(a[1]), "r"(a[2]), "r"(a[3]), "r"(b[0]), "r"(b[1]));
}
__device__ __forceinline__ void ins3(float v, int i, float* a, int* ai) {
    if (v < a[0] || (v == a[0] && i < ai[0])) {
        a[2] = a[1]; ai[2] = ai[1]; a[1] = a[0]; ai[1] = ai[0]; a[0] = v; ai[0] = i;
    } else if (v < a[1] || (v == a[1] && i < ai[1])) {
        a[2] = a[1]; ai[2] = ai[1]; a[1] = v; ai[1] = i;
    } else if (v < a[2] || (v == a[2] && i < ai[2])) {
        a[2] = v; ai[2] = i;
    }
}

// warp-parallel exact fp64 score (wrow contiguous)
__device__ double wscore64(const float* __restrict__ xrow, const float* __restrict__ wrow, int lane) {
    double dot = 0.0, ws = 0.0;
    #pragma unroll
    for (int j = lane; j < ND; j += 32) {
        double w = (double)wrow[j];
        dot += (double)xrow[j] * w;
        ws  += w * w;
    }
    double sc = ws - 2.0 * dot;
    #pragma unroll
    for (int off = 16; off > 0; off >>= 1)
        sc += __shfl_down_sync(0xFFFFFFFFu, sc, off);
    return __shfl_sync(0xFFFFFFFFu, sc, 0);
}

// ---- prep: transpose (blocks 0..4095) + wsq from E (blocks 4096..4159), one launch ----
__global__ void prep_kernel(const float* __restrict__ E) {
    if (blockIdx.x < 4096) {
        __shared__ float t[32][33];
        int bi = blockIdx.x;
        int v = bi >> 8, rem = bi & 255;
        int k0 = (rem & 31) * 32, d0 = (rem >> 5) * 32;
        int tx = threadIdx.x, ty = threadIdx.y;
        const float* Ev = E + (size_t)v * ND * NK;
        #pragma unroll
        for (int j = 0; j < 32; j += 8) t[ty + j][tx] = Ev[(size_t)(d0 + ty + j) * NK + k0 + tx];
        __syncthreads();
        float* Wv = g_Wt + (size_t)v * NK * ND;
        __half* Hv = g_Wh + (size_t)v * NK * ND;
        #pragma unroll
        for (int j = 0; j < 32; j += 8) {
            float val = t[tx][ty + j];
            size_t o = (size_t)(k0 + ty + j) * ND + d0 + tx;
            Wv[o] = val;
            Hv[o] = __float2half_rn(val);
        }
    } else {
        // wsq: one thread per (v,k); loads coalesced across k
        int tid = threadIdx.y * 32 + threadIdx.x;
        int t = (blockIdx.x - 4096) * 256 + tid;       // 0..16383
        int v = t >> 10, k = t & (NK - 1);
        const float* p = E + (size_t)v * ND * NK + k;
        double s = 0.0;
        #pragma unroll 8
        for (int d = 0; d < ND; ++d) { float w = p[(size_t)d * NK]; s += (double)w * (double)w; }
        g_wsq[t] = (float)s;
        if (t == 0) { g_accum = 0.0; g_fix_count = 0; g_pair_count = 0; }
    }
}

// ---- main: fp16 HMMA + top-3 classification + fused gather/loss + fused X conversion ----
// grid (NN/128, NV), 256 thr = 8 warps (4M x 2N), warp tile 32x32, 2 CTAs/SM
__global__ void __launch_bounds__(256, 2)
gemm_argmin_kernel(const float* __restrict__ X, float* __restrict__ out) {
    extern __shared__ char smem[];
    const uint32_t sb = smem_u32(smem);
    const int tid = threadIdx.x, lane = tid & 31, wid = tid >> 5;
    const int wm = wid & 3, wn = wid >> 2;
    const int g = lane >> 2, tg = lane & 3;
    const int v = blockIdx.y, row0 = blockIdx.x * 128;

    {
        float* sw = (float*)(smem + WSQ_S);
        #pragma unroll
        for (int q = 0; q < 4; ++q) sw[tid + q * 256] = g_wsq[v * NK + tid + q * 256];
    }

    auto issueB = [&](int i) {
        int nc = i >> 2, dc = i & 3, buf = i % 3;
        size_t bb = ((size_t)v * NK + nc * 64) * ND + dc * 64;
        #pragma unroll
        for (int j = 0; j < 2; ++j) {
            int q = tid * 2 + j;
            int r = q >> 3, c = q & 7;
            cpa16(sb + BOFF + buf * BTILB + r * ROWB + c * 16,
                  (const char*)g_Wh + (bb + (size_t)r * ND + c * 8) * 2);
        }
        CP_COMMIT();
    };

    issueB(0);
    issueB(1);

    // A: load fp32 X, convert to fp16, store into resident padded tiles
    const size_t abase = ((size_t)v * NN + row0) * ND;
    {
        #pragma unroll
        for (int j = 0; j < 32; ++j) {
            int q = tid + j * 256;
            int r = q >> 6;
            int dc = (q >> 4) & 3;
            int c = q & 15;
            float4 x = *(const float4*)(X + abase + (size_t)r * ND + dc * 64 + c * 4);
            __half2 h0 = __floats2half2_rn(x.x, x.y);
            __half2 h1 = __floats2half2_rn(x.z, x.w);
            char* dst = smem + AOFF + dc * ATILB + r * ROWB + c * 8;
            *(__half2*)(dst)     = h0;
            *(__half2*)(dst + 4) = h1;
        }
    }

    float tv[4][3]; int ti[4][3];
    #pragma unroll
    for (int s = 0; s < 4; ++s)
        #pragma unroll
        for (int j = 0; j < 3; ++j) { tv[s][j] = FLT_MAX; ti[s][j] = 0x7FFFFFFF; }

    const float* sw = (const float*)(smem + WSQ_S);

    const uint32_t aLane = (uint32_t)((wm * 32 + (lane & 15)) * ROWB + ((lane >> 4) << 4));
    const uint32_t bLane = (uint32_t)((wn * 32 + ((lane >> 4) << 3) + (lane & 7)) * ROWB
                                      + (((lane >> 3) & 1) << 4));

    for (int nc = 0; nc < 16; ++nc) {
        float c[2][4][4];
        #pragma unroll
        for (int mf = 0; mf < 2; ++mf)
            #pragma unroll
            for (int nf = 0; nf < 4; ++nf)
                #pragma unroll
                for (int e = 0; e < 4; ++e) c[mf][nf][e] = 0.0f;

        for (int dc = 0; dc < 4; ++dc) {
            int ph = nc * 4 + dc;
            if (ph < 63) { CP_WAIT1(); } else { CP_WAIT0(); }
            __syncthreads();
            if (ph < 62) issueB(ph + 2);

            const uint32_t aB = sb + AOFF + dc * ATILB + aLane;
            const uint32_t bB = sb + BOFF + (ph % 3) * BTILB + bLane;
            #pragma unroll
            for (int ks = 0; ks < 4; ++ks) {
                uint32_t A0[4], A1[4], B0[4], B1[4];
                ldsm4(A0, aB + ks * 32);
                ldsm4(A1, aB + 16 * ROWB + ks * 32);
                ldsm4(B0, bB + ks * 32);
                ldsm4(B1, bB + 16 * ROWB + ks * 32);
                mma16816(c[0][0], A0, B0);     mma16816(c[0][1], A0, B0 + 2);
                mma16816(c[0][2], A0, B1);     mma16816(c[0][3], A0, B1 + 2);
                mma16816(c[1][0], A1, B0);     mma16816(c[1][1], A1, B0 + 2);
                mma16816(c[1][2], A1, B1);     mma16816(c[1][3], A1, B1 + 2);
            }
        }

        #pragma unroll
        for (int mf = 0; mf < 2; ++mf)
            #pragma unroll
            for (int nf = 0; nf < 4; ++nf)
                #pragma unroll
                for (int e = 0; e < 4; ++e) {
                    int col  = nc * 64 + wn * 32 + nf * 8 + tg * 2 + (e & 1);
                    int slot = mf * 2 + (e >> 1);
                    float sc = sw[col] - 2.0f * c[mf][nf][e];
                    float* a = tv[slot]; int* ai = ti[slot];
                    if (sc < a[2]) {
                        if (sc < a[1]) {
                            a[2] = a[1]; ai[2] = ai[1];
                            if (sc < a[0]) { a[1] = a[0]; ai[1] = ai[0]; a[0] = sc; ai[0] = col; }
                            else           { a[1] = sc; ai[1] = col; }
                        } else { a[2] = sc; ai[2] = col; }
                    }
                }
    }

    const unsigned m = 0xFFFFFFFFu;
    #pragma unroll
    for (int off = 1; off < 4; off <<= 1) {
        #pragma unroll
        for (int s = 0; s < 4; ++s) {
            float ov[3]; int oi[3];
            #pragma unroll
            for (int j = 0; j < 3; ++j) {
                ov[j] = __shfl_xor_sync(m, tv[s][j], off);
                oi[j] = __shfl_xor_sync(m, ti[s][j], off);
            }
            #pragma unroll
            for (int j = 0; j < 3; ++j) ins3(ov[j], oi[j], tv[s], ti[s]);
        }
    }

    float* mv = (float*)(smem + MRG);
    int*   mi = (int*)  (smem + MRG + 3072);
    __syncthreads();
    if (tg == 0) {
        #pragma unroll
        for (int s = 0; s < 4; ++s) {
            int rl = wm * 32 + (s >> 1) * 16 + g + (s & 1) * 8;
            #pragma unroll
            for (int j = 0; j < 3; ++j) {
                mv[(wn * 128 + rl) * 3 + j] = tv[s][j];
                mi[(wn * 128 + rl) * 3 + j] = ti[s][j];
            }
        }
    }
    __syncthreads();

    int provisional = 0;
    if (tid < 128) {
        float a[3]; int ai[3];
        #pragma unroll
        for (int j = 0; j < 3; ++j) { a[j] = mv[tid * 3 + j]; ai[j] = mi[tid * 3 + j]; }
        #pragma unroll
        for (int j = 0; j < 3; ++j)
            ins3(mv[(128 + tid) * 3 + j], mi[(128 + tid) * 3 + j], a, ai);

        int R = v * NN + row0 + tid;
        provisional = ai[0];
        g_idx[R] = ai[0];
        float gap2 = a[1] - a[0], gap3 = a[2] - a[0];
        if (gap3 < W1) {
            int slot = atomicAdd(&g_fix_count, 1);
            g_fix_rows[slot] = R;
        } else if (gap2 < W1) {
            int slot = atomicAdd(&g_pair_count, 1);
            g_pair_rows[slot] = R;
            g_pair_cands[slot] = make_int2(ai[0], ai[1]);
        }
    }

    // ---- fused gather + loss ----
    __syncthreads();
    int*   sk    = (int*)(smem + MRG);
    float* wsums = (float*)(smem + MRG + 512);
    if (tid < 128) sk[tid] = provisional;
    __syncthreads();

    float part = 0.0f;
    const float* Xv = X + ((size_t)v * NN + row0) * ND;
    float* Ov = out + ((size_t)v * NN + row0) * ND;
    for (int r = wid * 16; r < wid * 16 + 16; ++r) {
        int k = sk[r];
        const float4* wrow = (const float4*)(g_Wt + ((size_t)v * NK + k) * ND);
        const float4* xrow = (const float4*)(Xv + (size_t)r * ND);
        float4* orow = (float4*)(Ov + (size_t)r * ND);
        #pragma unroll
        for (int j = 0; j < 2; ++j) {
            float4 qv = wrow[lane + j * 32];
            float4 xv = xrow[lane + j * 32];
            orow[lane + j * 32] = qv;
            float dx = qv.x - xv.x, dy = qv.y - xv.y, dz = qv.z - xv.z, dw = qv.w - xv.w;
            part += dx * dx + dy * dy + dz * dz + dw * dw;
        }
    }
    #pragma unroll
    for (int off = 16; off > 0; off >>= 1) part += __shfl_down_sync(m, part, off);
    if (lane == 0) wsums[wid] = part;
    __syncthreads();
    if (tid == 0) {
        double t = 0.0;
        #pragma unroll
        for (int i = 0; i < 8; ++i) t += (double)wsums[i];
        atomicAdd(&g_accum, t);
    }
}

// ---- exact pair adjudication: candidates split across half-warps ----
__global__ void __launch_bounds__(256)
fixpair_kernel(const float* __restrict__ X, float* __restrict__ out) {
    int cnt = g_pair_count;
    int nw = gridDim.x * 8;
    int w = blockIdx.x * 8 + (threadIdx.x >> 5);
    int lane = threadIdx.x & 31;
    int half = lane >> 4, l16 = lane & 15;
    const unsigned m = 0xFFFFFFFFu;
    for (int e = w; e < cnt; e += nw) {
        int R = g_pair_rows[e];
        int2 cd = g_pair_cands[e];
        int v = R >> 13;
        const float* xrow = X + (size_t)R * ND;
        const float* Wv = g_Wt + (size_t)v * NK * ND;
        int k = half ? cd.y : cd.x;
        const float* wr = Wv + (size_t)k * ND;
        double dot = 0.0, ws = 0.0;
        #pragma unroll
        for (int j = l16; j < ND; j += 16) {
            double wv_ = (double)wr[j];
            dot += (double)xrow[j] * wv_;
            ws  += wv_ * wv_;
        }
        double sc = ws - 2.0 * dot;
        #pragma unroll
        for (int off = 8; off > 0; off >>= 1)
            sc += __shfl_down_sync(m, sc, off, 16);
        double s0 = __shfl_sync(m, sc, 0);
        double s1 = __shfl_sync(m, sc, 16);
        bool flip = (s1 < s0) || (s1 == s0 && cd.y < cd.x);
        if (flip) {
            const float4* wr2 = (const float4*)(Wv + (size_t)cd.y * ND);
            float4* orow = (float4*)(out + (size_t)R * ND);
            orow[lane] = wr2[lane];
            orow[lane + 32] = wr2[lane + 32];
            if (lane == 0) {
                g_idx[R] = cd.y;
                atomicAdd(&g_accum, s1 - s0);   // delta(sse) == delta(score)
            }
        }
    }
}

// ---- exact full-row rescore + correction for triple-flagged rows ----
__global__ void __launch_bounds__(256)
fix_kernel(const float* __restrict__ X, float* __restrict__ out) {
    __shared__ float xs[ND];
    __shared__ float wv[16];
    __shared__ int   wi[16];
    __shared__ int   s_kk, s_old;
    __shared__ double s_delta;
    int cnt = g_fix_count;
    for (int f = blockIdx.x; f < cnt; f += gridDim.x) {
        int R = g_fix_rows[f];
        int v = R >> 13;
        __syncthreads();
        xs[threadIdx.x] = X[(size_t)R * ND + threadIdx.x];
        __syncthreads();

        float b = FLT_MAX, s = FLT_MAX; int bi = 0x7FFFFFFF, si = 0x7FFFFFFF;
        #pragma unroll
        for (int kk = 0; kk < 4; ++kk) {
            int k = threadIdx.x * 4 + kk;
            const float* w = g_Wt + ((size_t)v * NK + k) * ND;
            float dot = 0.0f;
            #pragma unroll 8
            for (int d = 0; d < ND; ++d) dot = fmaf(xs[d], w[d], dot);
            float sc = g_wsq[v * NK + k] - 2.0f * dot;
            if (sc < b || (sc == b && k < bi)) { s = b; si = bi; b = sc; bi = k; }
            else if (sc < s || (sc == s && k < si)) { s = sc; si = k; }
        }
        const unsigned m = 0xFFFFFFFFu;
        #pragma unroll
        for (int off = 1; off < 32; off <<= 1) {
            float ob = __shfl_xor_sync(m, b, off);  int obi = __shfl_xor_sync(m, bi, off);
            float os = __shfl_xor_sync(m, s, off);  int osi = __shfl_xor_sync(m, si, off);
            bool tko = (ob < b) || (ob == b && obi < bi);
            float lb = tko ? b : ob; int lbi = tko ? bi : obi;
            float ws_ = tko ? os : s; int wsi = tko ? osi : si;
            if (tko) { b = ob; bi = obi; }
            if (ws_ < lb || (ws_ == lb && wsi < lbi)) { s = ws_; si = wsi; }
            else                                      { s = lb;  si = lbi; }
        }
        int wrp = threadIdx.x >> 5;
        if ((threadIdx.x & 31) == 0) { wv[wrp * 2] = b; wv[wrp * 2 + 1] = s; wi[wrp * 2] = bi; wi[wrp * 2 + 1] = si; }
        __syncthreads();
        if (threadIdx.x == 0) {
            float B = FLT_MAX, S = FLT_MAX; int Bi = 0x7FFFFFFF, Si = 0x7FFFFFFF;
            for (int q = 0; q < 16; ++q) {
                float vq = wv[q]; int iq = wi[q];
                if (vq < B || (vq == B && iq < Bi)) { S = B; Si = Bi; B = vq; Bi = iq; }
                else if (vq < S || (vq == S && iq < Si)) { S = vq; Si = iq; }
            }
            wv[0] = S - B; wi[0] = Bi; wi[1] = Si;
        }
        __syncthreads();
        if (threadIdx.x < 32) {
            int lane = threadIdx.x;
            int Bi = wi[0], Si = wi[1];
            const float* Wv = g_Wt + (size_t)v * NK * ND;
            int kk = Bi;
            if (wv[0] < MARGIN) {
                double sb2 = wscore64(xs, Wv + (size_t)Bi * ND, lane);
                double ss2 = wscore64(xs, Wv + (size_t)Si * ND, lane);
                if (ss2 < sb2 || (ss2 == sb2 && Si < Bi)) kk = Si;
            }
            int old = g_idx[R];
            double delta = 0.0;
            if (kk != old) {
                double sn = wscore64(xs, Wv + (size_t)kk * ND, lane);
                double so = wscore64(xs, Wv + (size_t)old * ND, lane);
                delta = sn - so;
            }
            if (lane == 0) { s_kk = kk; s_old = old; s_delta = delta; }
        }
        __syncthreads();
        if (s_kk != s_old) {
            out[(size_t)R * ND + threadIdx.x] = g_Wt[((size_t)v * NK + s_kk) * ND + threadIdx.x];
            if (threadIdx.x == 0) {
                g_idx[R] = s_kk;
                atomicAdd(&g_accum, s_delta);
            }
        }
        __syncthreads();
    }
}

// ---- loss writeback ----
__global__ void loss_kernel(float* __restrict__ out, long long out_size) {
    const long long VND = (long long)NV * NN * ND;
    double loss = 1.25 * g_accum / (double)VND;
    for (long long i = VND + threadIdx.x; i < out_size; i += blockDim.x)
        out[i] = (float)loss;
}

extern "C" void kernel_launch(void* const* d_in, const int* in_sizes, int n_in,
                              void* d_out, int out_size) {
    const float* X = (const float*)d_in[0];
    const float* E = (const float*)d_in[1];
    float* out = (float*)d_out;

    cudaFuncSetAttribute((const void*)gemm_argmin_kernel,
                         cudaFuncAttributeMaxDynamicSharedMemorySize, SMEM_TOTAL);

    prep_kernel<<<4160, dim3(32, 8)>>>(E);
    gemm_argmin_kernel<<<dim3(NN / 128, NV), 256, SMEM_TOTAL>>>(X, out);
    fixpair_kernel<<<512, 256>>>(X, out);
    fix_kernel<<<128, 256>>>(X, out);
    loss_kernel<<<1, 32>>>(out, (long long)out_size);
}

// round 17
// speedup vs baseline: 1.1644x; 1.1644x over previous
#include <cuda_runtime.h>
#include <cuda_fp16.h>
#include <cfloat>
#include <cstdint>

#define NV 16
#define NN 8192
#define ND 256
#define NK 1024
#define W1 0.26f          // coarse-score uncertainty window
#define MARGIN 0.05f      // fp32-exact pair-adjudication margin

// ---- smem layout (bytes) ----
#define ROWB   144
#define ATILB  18432
#define BTILB  9216
#define AOFF   0
#define BOFF   73728
#define WSQ_S  101376
#define MRG    105472
#define SMEM_TOTAL 111616

// ---- device scratch ----
__device__ float  g_wsq[NV * NK];
__device__ float  g_Wt[(size_t)NV * NK * ND];                    // [V][K][D] fp32
__device__ __align__(256) __half g_Wh[(size_t)NV * NK * ND];     // Wt fp16
__device__ int    g_idx[NV * NN];
__device__ int    g_fix_count;
__device__ int    g_pair_count;
__device__ int    g_fix_rows[NV * NN];
__device__ int    g_pair_rows[NV * NN];
__device__ int2   g_pair_cands[NV * NN];
__device__ double g_accum;

// ---- helpers ----
__device__ __forceinline__ uint32_t smem_u32(const void* p) {
    uint32_t a;
    asm("{ .reg .u64 t; cvta.to.shared.u64 t, %1; cvt.u32.u64 %0, t; }" : "=r"(a) : "l"(p));
    return a;
}
__device__ __forceinline__ void cpa16(uint32_t dst, const void* src) {
    asm volatile("cp.async.cg.shared.global [%0], [%1], 16;" :: "r"(dst), "l"(src));
}
#define CP_COMMIT() asm volatile("cp.async.commit_group;" ::: "memory")
#define CP_WAIT1()  asm volatile("cp.async.wait_group 1;" ::: "memory")
#define CP_WAIT0()  asm volatile("cp.async.wait_group 0;" ::: "memory")
__device__ __forceinline__ void ldsm4(uint32_t* r, uint32_t a) {
    asm volatile("ldmatrix.sync.aligned.m8n8.x4.shared.b16 {%0,%1,%2,%3}, [%4];"
        : "=r"(r[0]), "=r"(r[1]), "=r"(r[2]), "=r"(r[3]) : "r"(a));
}
__device__ __forceinline__ void mma16816(float* c, const uint32_t* a, const uint32_t* b) {
    asm volatile("mma.sync.aligned.m16n8k16.row.col.f32.f16.f16.f32 "
        "{%0,%1,%2,%3}, {%4,%5,%6,%7}, {%8,%9}, {%0,%1,%2,%3};"
        : "+f"(c[0]), "+f"(c[1]), "+f"(c[2]), "+f"(c[3])
        : "r"(a[0]), "r"(a[1]), "r"(a[2]), "r"(a[3]), "r"(b[0]), "r"(b[1]));
}
__device__ __forceinline__ void ins3(float v, int i, float* a, int* ai) {
    if (v < a[0] || (v == a[0] && i < ai[0])) {
        a[2] = a[1]; ai[2] = ai[1]; a[1] = a[0]; ai[1] = ai[0]; a[0] = v; ai[0] = i;
    } else if (v < a[1] || (v == a[1] && i < ai[1])) {
        a[2] = a[1]; ai[2] = ai[1]; a[1] = v; ai[1] = i;
    } else if (v < a[2] || (v == a[2] && i < ai[2])) {
        a[2] = v; ai[2] = i;
    }
}

// warp-parallel exact fp64 score (wrow contiguous)
__device__ double wscore64(const float* __restrict__ xrow, const float* __restrict__ wrow, int lane) {
    double dot = 0.0, ws = 0.0;
    #pragma unroll
    for (int j = lane; j < ND; j += 32) {
        double w = (double)wrow[j];
        dot += (double)xrow[j] * w;
        ws  += w * w;
    }
    double sc = ws - 2.0 * dot;
    #pragma unroll
    for (int off = 16; off > 0; off >>= 1)
        sc += __shfl_down_sync(0xFFFFFFFFu, sc, off);
    return __shfl_sync(0xFFFFFFFFu, sc, 0);
}

// ---- prep: transpose (blocks 0..4095) + wsq from E (blocks 4096..4159), one launch ----
__global__ void prep_kernel(const float* __restrict__ E) {
    if (blockIdx.x < 4096) {
        __shared__ float t[32][33];
        int bi = blockIdx.x;
        int v = bi >> 8, rem = bi & 255;
        int k0 = (rem & 31) * 32, d0 = (rem >> 5) * 32;
        int tx = threadIdx.x, ty = threadIdx.y;
        const float* Ev = E + (size_t)v * ND * NK;
        #pragma unroll
        for (int j = 0; j < 32; j += 8) t[ty + j][tx] = Ev[(size_t)(d0 + ty + j) * NK + k0 + tx];
        __syncthreads();
        float* Wv = g_Wt + (size_t)v * NK * ND;
        __half* Hv = g_Wh + (size_t)v * NK * ND;
        #pragma unroll
        for (int j = 0; j < 32; j += 8) {
            float val = t[tx][ty + j];
            size_t o = (size_t)(k0 + ty + j) * ND + d0 + tx;
            Wv[o] = val;
            Hv[o] = __float2half_rn(val);
        }
    } else {
        int tid = threadIdx.y * 32 + threadIdx.x;
        int t = (blockIdx.x - 4096) * 256 + tid;       // 0..16383
        int v = t >> 10, k = t & (NK - 1);
        const float* p = E + (size_t)v * ND * NK + k;
        double s = 0.0;
        #pragma unroll 8
        for (int d = 0; d < ND; ++d) { float w = p[(size_t)d * NK]; s += (double)w * (double)w; }
        g_wsq[t] = (float)s;
        if (t == 0) { g_accum = 0.0; g_fix_count = 0; g_pair_count = 0; }
    }
}

// ---- main: fp16 HMMA + top-3 classification + fused gather/loss + fused X conversion ----
// grid (NN/128, NV), 256 thr = 8 warps (4M x 2N), warp tile 32x32, 2 CTAs/SM
__global__ void __launch_bounds__(256, 2)
gemm_argmin_kernel(const float* __restrict__ X, float* __restrict__ out) {
    extern __shared__ char smem[];
    const uint32_t sb = smem_u32(smem);
    const int tid = threadIdx.x, lane = tid & 31, wid = tid >> 5;
    const int wm = wid & 3, wn = wid >> 2;
    const int g = lane >> 2, tg = lane & 3;
    const int v = blockIdx.y, row0 = blockIdx.x * 128;

    {
        float* sw = (float*)(smem + WSQ_S);
        #pragma unroll
        for (int q = 0; q < 4; ++q) sw[tid + q * 256] = g_wsq[v * NK + tid + q * 256];
    }

    auto issueB = [&](int i) {
        int nc = i >> 2, dc = i & 3, buf = i % 3;
        size_t bb = ((size_t)v * NK + nc * 64) * ND + dc * 64;
        #pragma unroll
        for (int j = 0; j < 2; ++j) {
            int q = tid * 2 + j;
            int r = q >> 3, c = q & 7;
            cpa16(sb + BOFF + buf * BTILB + r * ROWB + c * 16,
                  (const char*)g_Wh + (bb + (size_t)r * ND + c * 8) * 2);
        }
        CP_COMMIT();
    };

    issueB(0);
    issueB(1);

    // A: load fp32 X, convert to fp16, store into resident padded tiles
    const size_t abase = ((size_t)v * NN + row0) * ND;
    {
        #pragma unroll
        for (int j = 0; j < 32; ++j) {
            int q = tid + j * 256;
            int r = q >> 6;
            int dc = (q >> 4) & 3;
            int c = q & 15;
            float4 x = *(const float4*)(X + abase + (size_t)r * ND + dc * 64 + c * 4);
            __half2 h0 = __floats2half2_rn(x.x, x.y);
            __half2 h1 = __floats2half2_rn(x.z, x.w);
            char* dst = smem + AOFF + dc * ATILB + r * ROWB + c * 8;
            *(__half2*)(dst)     = h0;
            *(__half2*)(dst + 4) = h1;
        }
    }

    float tv[4][3]; int ti[4][3];
    #pragma unroll
    for (int s = 0; s < 4; ++s)
        #pragma unroll
        for (int j = 0; j < 3; ++j) { tv[s][j] = FLT_MAX; ti[s][j] = 0x7FFFFFFF; }

    const float* sw = (const float*)(smem + WSQ_S);

    const uint32_t aLane = (uint32_t)((wm * 32 + (lane & 15)) * ROWB + ((lane >> 4) << 4));
    const uint32_t bLane = (uint32_t)((wn * 32 + ((lane >> 4) << 3) + (lane & 7)) * ROWB
                                      + (((lane >> 3) & 1) << 4));

    for (int nc = 0; nc < 16; ++nc) {
        float c[2][4][4];
        #pragma unroll
        for (int mf = 0; mf < 2; ++mf)
            #pragma unroll
            for (int nf = 0; nf < 4; ++nf)
                #pragma unroll
                for (int e = 0; e < 4; ++e) c[mf][nf][e] = 0.0f;

        for (int dc = 0; dc < 4; ++dc) {
            int ph = nc * 4 + dc;
            if (ph < 63) { CP_WAIT1(); } else { CP_WAIT0(); }
            __syncthreads();
            if (ph < 62) issueB(ph + 2);

            const uint32_t aB = sb + AOFF + dc * ATILB + aLane;
            const uint32_t bB = sb + BOFF + (ph % 3) * BTILB + bLane;
            #pragma unroll
            for (int ks = 0; ks < 4; ++ks) {
                uint32_t A0[4], A1[4], B0[4], B1[4];
                ldsm4(A0, aB + ks * 32);
                ldsm4(A1, aB + 16 * ROWB + ks * 32);
                ldsm4(B0, bB + ks * 32);
                ldsm4(B1, bB + 16 * ROWB + ks * 32);
                mma16816(c[0][0], A0, B0);     mma16816(c[0][1], A0, B0 + 2);
                mma16816(c[0][2], A0, B1);     mma16816(c[0][3], A0, B1 + 2);
                mma16816(c[1][0], A1, B0);     mma16816(c[1][1], A1, B0 + 2);
                mma16816(c[1][2], A1, B1);     mma16816(c[1][3], A1, B1 + 2);
            }
        }

        #pragma unroll
        for (int mf = 0; mf < 2; ++mf)
            #pragma unroll
            for (int nf = 0; nf < 4; ++nf)
                #pragma unroll
                for (int e = 0; e < 4; ++e) {
                    int col  = nc * 64 + wn * 32 + nf * 8 + tg * 2 + (e & 1);
                    int slot = mf * 2 + (e >> 1);
                    float sc = sw[col] - 2.0f * c[mf][nf][e];
                    float* a = tv[slot]; int* ai = ti[slot];
                    if (sc < a[2]) {
                        if (sc < a[1]) {
                            a[2] = a[1]; ai[2] = ai[1];
                            if (sc < a[0]) { a[1] = a[0]; ai[1] = ai[0]; a[0] = sc; ai[0] = col; }
                            else           { a[1] = sc; ai[1] = col; }
                        } else { a[2] = sc; ai[2] = col; }
                    }
                }
    }

    const unsigned m = 0xFFFFFFFFu;
    #pragma unroll
    for (int off = 1; off < 4; off <<= 1) {
        #pragma unroll
        for (int s = 0; s < 4; ++s) {
            float ov[3]; int oi[3];
            #pragma unroll
            for (int j = 0; j < 3; ++j) {
                ov[j] = __shfl_xor_sync(m, tv[s][j], off);
                oi[j] = __shfl_xor_sync(m, ti[s][j], off);
            }
            #pragma unroll
            for (int j = 0; j < 3; ++j) ins3(ov[j], oi[j], tv[s], ti[s]);
        }
    }

    float* mv = (float*)(smem + MRG);
    int*   mi = (int*)  (smem + MRG + 3072);
    __syncthreads();
    if (tg == 0) {
        #pragma unroll
        for (int s = 0; s < 4; ++s) {
            int rl = wm * 32 + (s >> 1) * 16 + g + (s & 1) * 8;
            #pragma unroll
            for (int j = 0; j < 3; ++j) {
                mv[(wn * 128 + rl) * 3 + j] = tv[s][j];
                mi[(wn * 128 + rl) * 3 + j] = ti[s][j];
            }
        }
    }
    __syncthreads();

    int provisional = 0;
    if (tid < 128) {
        float a[3]; int ai[3];
        #pragma unroll
        for (int j = 0; j < 3; ++j) { a[j] = mv[tid * 3 + j]; ai[j] = mi[tid * 3 + j]; }
        #pragma unroll
        for (int j = 0; j < 3; ++j)
            ins3(mv[(128 + tid) * 3 + j], mi[(128 + tid) * 3 + j], a, ai);

        int R = v * NN + row0 + tid;
        provisional = ai[0];
        g_idx[R] = ai[0];
        float gap2 = a[1] - a[0], gap3 = a[2] - a[0];
        if (gap3 < W1) {
            int slot = atomicAdd(&g_fix_count, 1);
            g_fix_rows[slot] = R;
        } else if (gap2 < W1) {
            int slot = atomicAdd(&g_pair_count, 1);
            g_pair_rows[slot] = R;
            g_pair_cands[slot] = make_int2(ai[0], ai[1]);
        }
    }

    // ---- fused gather + loss ----
    __syncthreads();
    int*   sk    = (int*)(smem + MRG);
    float* wsums = (float*)(smem + MRG + 512);
    if (tid < 128) sk[tid] = provisional;
    __syncthreads();

    float part = 0.0f;
    const float* Xv = X + ((size_t)v * NN + row0) * ND;
    float* Ov = out + ((size_t)v * NN + row0) * ND;
    for (int r = wid * 16; r < wid * 16 + 16; ++r) {
        int k = sk[r];
        const float4* wrow = (const float4*)(g_Wt + ((size_t)v * NK + k) * ND);
        const float4* xrow = (const float4*)(Xv + (size_t)r * ND);
        float4* orow = (float4*)(Ov + (size_t)r * ND);
        #pragma unroll
        for (int j = 0; j < 2; ++j) {
            float4 qv = wrow[lane + j * 32];
            float4 xv = xrow[lane + j * 32];
            orow[lane + j * 32] = qv;
            float dx = qv.x - xv.x, dy = qv.y - xv.y, dz = qv.z - xv.z, dw = qv.w - xv.w;
            part += dx * dx + dy * dy + dz * dz + dw * dw;
        }
    }
    #pragma unroll
    for (int off = 16; off > 0; off >>= 1) part += __shfl_down_sync(m, part, off);
    if (lane == 0) wsums[wid] = part;
    __syncthreads();
    if (tid == 0) {
        double t = 0.0;
        #pragma unroll
        for (int i = 0; i < 8; ++i) t += (double)wsums[i];
        atomicAdd(&g_accum, t);
    }
}

// ---- exact pair adjudication: candidates split across half-warps ----
__global__ void __launch_bounds__(256)
fixpair_kernel(const float* __restrict__ X, float* __restrict__ out) {
    int cnt = g_pair_count;
    int nw = gridDim.x * 8;
    int w = blockIdx.x * 8 + (threadIdx.x >> 5);
    int lane = threadIdx.x & 31;
    int half = lane >> 4, l16 = lane & 15;
    const unsigned m = 0xFFFFFFFFu;
    for (int e = w; e < cnt; e += nw) {
        int R = g_pair_rows[e];
        int2 cd = g_pair_cands[e];
        int v = R >> 13;
        const float* xrow = X + (size_t)R * ND;
        const float* Wv = g_Wt + (size_t)v * NK * ND;
        int k = half ? cd.y : cd.x;
        const float* wr = Wv + (size_t)k * ND;
        double dot = 0.0, ws = 0.0;
        #pragma unroll
        for (int j = l16; j < ND; j += 16) {
            double wv_ = (double)wr[j];
            dot += (double)xrow[j] * wv_;
            ws  += wv_ * wv_;
        }
        double sc = ws - 2.0 * dot;
        #pragma unroll
        for (int off = 8; off > 0; off >>= 1)
            sc += __shfl_down_sync(m, sc, off, 16);
        double s0 = __shfl_sync(m, sc, 0);
        double s1 = __shfl_sync(m, sc, 16);
        bool flip = (s1 < s0) || (s1 == s0 && cd.y < cd.x);
        if (flip) {
            const float4* wr2 = (const float4*)(Wv + (size_t)cd.y * ND);
            float4* orow = (float4*)(out + (size_t)R * ND);
            orow[lane] = wr2[lane];
            orow[lane + 32] = wr2[lane + 32];
            if (lane == 0) {
                g_idx[R] = cd.y;
                atomicAdd(&g_accum, s1 - s0);   // delta(sse) == delta(score)
            }
        }
    }
}

// ---- exact full-row rescore: coalesced warp-per-candidate GEMV ----
__global__ void __launch_bounds__(256)
fix_kernel(const float* __restrict__ X, float* __restrict__ out) {
    __shared__ float xs[ND];
    __shared__ float wv[16];
    __shared__ int   wi[16];
    __shared__ int   s_kk, s_old;
    __shared__ double s_delta;
    const unsigned m = 0xFFFFFFFFu;
    const int tid = threadIdx.x, lane = tid & 31, wid = tid >> 5;
    int cnt = g_fix_count;
    for (int f = blockIdx.x; f < cnt; f += gridDim.x) {
        int R = g_fix_rows[f];
        int v = R >> 13;
        __syncthreads();
        xs[tid] = X[(size_t)R * ND + tid];
        __syncthreads();

        // each lane caches its 8 x-values (d = lane*8 .. +7)
        float x[8];
        #pragma unroll
        for (int j = 0; j < 8; ++j) x[j] = xs[lane * 8 + j];

        const float* Wv = g_Wt + (size_t)v * NK * ND;
        const float* wsqv = g_wsq + v * NK;
        float b = FLT_MAX, s = FLT_MAX; int bi = 0x7FFFFFFF, si = 0x7FFFFFFF;

        // warp handles 2 candidates per iteration; coalesced 1KB row reads
        for (int it = 0; it < 64; ++it) {
            int k0 = it * 16 + wid * 2;
            const float4* w0 = (const float4*)(Wv + (size_t)k0 * ND + lane * 8);
            const float4* w1 = (const float4*)(Wv + (size_t)(k0 + 1) * ND + lane * 8);
            float4 a0 = w0[0], b0 = w0[1];
            float4 a1 = w1[0], b1 = w1[1];
            float d0 = x[0]*a0.x + x[1]*a0.y + x[2]*a0.z + x[3]*a0.w
                     + x[4]*b0.x + x[5]*b0.y + x[6]*b0.z + x[7]*b0.w;
            float d1 = x[0]*a1.x + x[1]*a1.y + x[2]*a1.z + x[3]*a1.w
                     + x[4]*b1.x + x[5]*b1.y + x[6]*b1.z + x[7]*b1.w;
            #pragma unroll
            for (int off = 16; off > 0; off >>= 1) {
                d0 += __shfl_down_sync(m, d0, off);
                d1 += __shfl_down_sync(m, d1, off);
            }
            d0 = __shfl_sync(m, d0, 0);
            d1 = __shfl_sync(m, d1, 0);
            float sc0 = wsqv[k0]     - 2.0f * d0;
            float sc1 = wsqv[k0 + 1] - 2.0f * d1;
            // deterministic top-2 updates (ascending k within warp)
            if (sc0 < b || (sc0 == b && k0 < bi)) { s = b; si = bi; b = sc0; bi = k0; }
            else if (sc0 < s || (sc0 == s && k0 < si)) { s = sc0; si = k0; }
            int k1 = k0 + 1;
            if (sc1 < b || (sc1 == b && k1 < bi)) { s = b; si = bi; b = sc1; bi = k1; }
            else if (sc1 < s || (sc1 == s && k1 < si)) { s = sc1; si = k1; }
        }
        if (lane == 0) { wv[wid * 2] = b; wv[wid * 2 + 1] = s; wi[wid * 2] = bi; wi[wid * 2 + 1] = si; }
        __syncthreads();
        if (tid == 0) {
            float B = FLT_MAX, S = FLT_MAX; int Bi = 0x7FFFFFFF, Si = 0x7FFFFFFF;
            for (int q = 0; q < 16; ++q) {
                float vq = wv[q]; int iq = wi[q];
                if (vq < B || (vq == B && iq < Bi)) { S = B; Si = Bi; B = vq; Bi = iq; }
                else if (vq < S || (vq == S && iq < Si)) { S = vq; Si = iq; }
            }
            wv[0] = S - B; wi[0] = Bi; wi[1] = Si;
        }
        __syncthreads();
        if (tid < 32) {
            int Bi = wi[0], Si = wi[1];
            int kk = Bi;
            if (wv[0] < MARGIN) {
                double sb2 = wscore64(xs, Wv + (size_t)Bi * ND, lane);
                double ss2 = wscore64(xs, Wv + (size_t)Si * ND, lane);
                if (ss2 < sb2 || (ss2 == sb2 && Si < Bi)) kk = Si;
            }
            int old = g_idx[R];
            double delta = 0.0;
            if (kk != old) {
                double sn = wscore64(xs, Wv + (size_t)kk * ND, lane);
                double so = wscore64(xs, Wv + (size_t)old * ND, lane);
                delta = sn - so;
            }
            if (lane == 0) { s_kk = kk; s_old = old; s_delta = delta; }
        }
        __syncthreads();
        if (s_kk != s_old) {
            out[(size_t)R * ND + tid] = g_Wt[((size_t)v * NK + s_kk) * ND + tid];
            if (tid == 0) {
                g_idx[R] = s_kk;
                atomicAdd(&g_accum, s_delta);
            }
        }
        __syncthreads();
    }
}

// ---- loss writeback ----
__global__ void loss_kernel(float* __restrict__ out, long long out_size) {
    const long long VND = (long long)NV * NN * ND;
    double loss = 1.25 * g_accum / (double)VND;
    for (long long i = VND + threadIdx.x; i < out_size; i += blockDim.x)
        out[i] = (float)loss;
}

extern "C" void kernel_launch(void* const* d_in, const int* in_sizes, int n_in,
                              void* d_out, int out_size) {
    const float* X = (const float*)d_in[0];
    const float* E = (const float*)d_in[1];
    float* out = (float*)d_out;

    cudaFuncSetAttribute((const void*)gemm_argmin_kernel,
                         cudaFuncAttributeMaxDynamicSharedMemorySize, SMEM_TOTAL);

    prep_kernel<<<4160, dim3(32, 8)>>>(E);
    gemm_argmin_kernel<<<dim3(NN / 128, NV), 256, SMEM_TOTAL>>>(X, out);
    fixpair_kernel<<<512, 256>>>(X, out);
    fix_kernel<<<512, 256>>>(X, out);
    loss_kernel<<<1, 32>>>(out, (long long)out_size);
}